// round 11
// baseline (speedup 1.0000x reference)
#include <cuda_runtime.h>
#include <cstdint>

#define NV 4096
#define NE 16384
#define IN_V 128
#define OUT_V 128
#define IN_E 64

// ---------------- device global scratch (no allocation allowed) -------------
// g_Td / g_Tt hold tf32-rounded operands with each 16-float K-chunk PERMUTED
// to order [c0,c4,c8,c12, c1,c5,c9,c13, c2,c6,c10,c14, c3,c7,c11,c15] so one
// LDS.128 yields a thread's mma fragment elements for both k8 steps.
__device__ float g_A[(size_t)NV * NV];            // adjusted adjacency, 64 MB
__device__ float g_Td[(size_t)NV * NE];           // rna_tf32(T * diag), permuted
__device__ float g_Tt[(size_t)NV * NE];           // rna_tf32(T), permuted
__device__ float g_diag[NE];
__device__ float g_X[NV * OUT_V];

__device__ __forceinline__ uint32_t f2tf32(float f) {
    uint32_t u; asm("cvt.rna.tf32.f32 %0, %1;" : "=r"(u) : "f"(f)); return u;
}
__device__ __forceinline__ uint32_t s2u(const void* p) {
    uint32_t a;
    asm("{ .reg .u64 t; cvta.to.shared.u64 t, %1; cvt.u32.u64 %0, t; }" : "=r"(a) : "l"(p));
    return a;
}
__device__ __forceinline__ void cp16(uint32_t dst, const void* src) {
    asm volatile("cp.async.cg.shared.global [%0], [%1], 16;" :: "r"(dst), "l"(src) : "memory");
}

// ---------------------------------------------------------------------------
// K1: g_diag[e] = dot(H_e[e,:], p)
// ---------------------------------------------------------------------------
__global__ void k_diag(const float* __restrict__ He, const float* __restrict__ p) {
    __shared__ float sp[IN_E];
    if (threadIdx.x < IN_E) sp[threadIdx.x] = p[threadIdx.x];
    __syncthreads();
    int e = blockIdx.x * blockDim.x + threadIdx.x;
    const float* row = He + (size_t)e * IN_E;
    float acc = 0.f;
#pragma unroll
    for (int k = 0; k < IN_E; k++) acc += row[k] * sp[k];
    g_diag[e] = acc;
}

// ---------------------------------------------------------------------------
// K1b: permuted-K tf32 operands.
// ---------------------------------------------------------------------------
__global__ void __launch_bounds__(256) k_prep(const float* __restrict__ T) {
    size_t idx = (size_t)blockIdx.x * 256 + threadIdx.x;
    size_t o4 = idx * 4;
    int colin = (int)(o4 & (NE - 1));
    int g = (colin >> 2) & 3;
    size_t rowbase = o4 - colin;
    int b = (colin & ~15) + g;
    float t0 = T[rowbase + b];
    float t1 = T[rowbase + b + 4];
    float t2 = T[rowbase + b + 8];
    float t3 = T[rowbase + b + 12];
    float d0 = g_diag[b], d1 = g_diag[b + 4], d2 = g_diag[b + 8], d3 = g_diag[b + 12];
    float4 td, tt;
    td.x = __uint_as_float(f2tf32(t0 * d0)); td.y = __uint_as_float(f2tf32(t1 * d1));
    td.z = __uint_as_float(f2tf32(t2 * d2)); td.w = __uint_as_float(f2tf32(t3 * d3));
    tt.x = __uint_as_float(f2tf32(t0)); tt.y = __uint_as_float(f2tf32(t1));
    tt.z = __uint_as_float(f2tf32(t2)); tt.w = __uint_as_float(f2tf32(t3));
    *(float4*)(g_Td + o4) = td;
    *(float4*)(g_Tt + o4) = tt;
}

// ---------------------------------------------------------------------------
// K2: g_X = H_v @ weight
// ---------------------------------------------------------------------------
__global__ void k_hvw(const float* __restrict__ Hv, const float* __restrict__ W) {
    int i = blockIdx.x, j = threadIdx.x;
    const float* hr = Hv + i * IN_V;
    float acc = 0.f;
#pragma unroll 16
    for (int k = 0; k < IN_V; k++) acc += hr[k] * W[k * OUT_V + j];
    g_X[i * OUT_V + j] = acc;
}

// ---------------------------------------------------------------------------
// K3: symmetric tf32 GEMM, upper-triangle tiles.
//     BK=32 per stage (halved barrier count), 3-stage cp.async pipeline,
//     128B rows with XOR-by-(row&7) chunk swizzle, conflict-free LDS.128.
// ---------------------------------------------------------------------------
constexpr int BM = 128;
constexpr int BK2 = 32;                      // K floats per stage
constexpr int ROWB = 128;                    // bytes per smem row (32 floats)
constexpr int HALF_B = BM * ROWB;            // 16384
constexpr int STAGE_B = 2 * HALF_B;          // 32768 (A half + B half)
constexpr int NSTG = 3;
constexpr int SMEM_G1 = NSTG * STAGE_B;      // 98304 (>= 66048 epilogue)
constexpr int NT1 = NV / BM;                 // 32
constexpr int NPAIR = NT1 * (NT1 + 1) / 2;   // 528
constexpr int NK2 = NE / BK2;                // 512
constexpr int STR = 129;                     // epilogue staging stride

__global__ void __launch_bounds__(256, 2) k_gemm1(const float* __restrict__ adj) {
    extern __shared__ char smem[];
    const uint32_t sbase = s2u(smem);

    // triangular decode: pid -> (ti, tj), ti <= tj
    int ti = 0, rem = blockIdx.x;
    while (rem >= NT1 - ti) { rem -= NT1 - ti; ti++; }
    const int tj = ti + rem;
    const int bm = ti * BM, bn = tj * BM;

    const int tid  = threadIdx.x;
    const int lane = tid & 31;
    const int warp = tid >> 5;
    const int wm = warp & 3;
    const int wn = warp >> 2;
    const int fr = lane >> 2;                 // 0..7
    const int fc = lane & 3;                  // 0..3
    // per-thread constant swizzled byte offsets for the two K16 halves
    const int sw0 = ((fc ^ fr) & 7) * 16;
    const int sw1 = (((4 + fc) ^ fr) & 7) * 16;

    float acc[2][8][4];
#pragma unroll
    for (int i = 0; i < 2; i++)
#pragma unroll
        for (int j = 0; j < 8; j++)
#pragma unroll
            for (int k = 0; k < 4; k++) acc[i][j][k] = 0.f;

    // cp.async mapping: 256 threads; row = tid>>1 (0..127), 4 chunks of 16B
    const int lrow = tid >> 1;
    const int cb4  = (tid & 1) * 4;           // chunk base 0 or 4
    const float* gA = g_Td + (size_t)(bm + lrow) * NE + cb4 * 4;
    const float* gB = g_Tt + (size_t)(bn + lrow) * NE + cb4 * 4;
    const uint32_t rowoff = (uint32_t)(lrow * ROWB);
    uint32_t sw[4];
#pragma unroll
    for (int i = 0; i < 4; i++) sw[i] = (uint32_t)((((cb4 + i) ^ lrow) & 7) * 16);

    auto ISSUE = [&](int s, int kc) {
        const uint32_t base  = sbase + s * STAGE_B + rowoff;
        const uint32_t baseB = base + HALF_B;
        const float* pa = gA + (size_t)kc * BK2;
        const float* pb = gB + (size_t)kc * BK2;
#pragma unroll
        for (int i = 0; i < 4; i++) cp16(base + sw[i], pa + i * 4);
#pragma unroll
        for (int i = 0; i < 4; i++) cp16(baseB + sw[i], pb + i * 4);
        asm volatile("cp.async.commit_group;" ::: "memory");
    };

    auto COMPUTE_H = [&](const char* As, const char* Bs, int swoff) {
        float4 a0[2], a1[2];
#pragma unroll
        for (int mt = 0; mt < 2; mt++) {
            int r0 = wm * 32 + mt * 16 + fr;
            a0[mt] = *(const float4*)(As + r0 * ROWB + swoff);
            a1[mt] = *(const float4*)(As + (r0 + 8) * ROWB + swoff);
        }
        float4 bv[8];
#pragma unroll
        for (int nt = 0; nt < 8; nt++) {
            int r = wn * 64 + nt * 8 + fr;
            bv[nt] = *(const float4*)(Bs + r * ROWB + swoff);
        }
#pragma unroll
        for (int mt = 0; mt < 2; mt++) {
            uint32_t afk0[4] = { __float_as_uint(a0[mt].x), __float_as_uint(a1[mt].x),
                                 __float_as_uint(a0[mt].y), __float_as_uint(a1[mt].y) };
            uint32_t afk8[4] = { __float_as_uint(a0[mt].z), __float_as_uint(a1[mt].z),
                                 __float_as_uint(a0[mt].w), __float_as_uint(a1[mt].w) };
#pragma unroll
            for (int nt = 0; nt < 8; nt++) {
                asm volatile(
                    "mma.sync.aligned.m16n8k8.row.col.f32.tf32.tf32.f32 "
                    "{%0,%1,%2,%3}, {%4,%5,%6,%7}, {%8,%9}, {%0,%1,%2,%3};\n"
                    : "+f"(acc[mt][nt][0]), "+f"(acc[mt][nt][1]),
                      "+f"(acc[mt][nt][2]), "+f"(acc[mt][nt][3])
                    : "r"(afk0[0]), "r"(afk0[1]), "r"(afk0[2]), "r"(afk0[3]),
                      "r"(__float_as_uint(bv[nt].x)), "r"(__float_as_uint(bv[nt].y)));
                asm volatile(
                    "mma.sync.aligned.m16n8k8.row.col.f32.tf32.tf32.f32 "
                    "{%0,%1,%2,%3}, {%4,%5,%6,%7}, {%8,%9}, {%0,%1,%2,%3};\n"
                    : "+f"(acc[mt][nt][0]), "+f"(acc[mt][nt][1]),
                      "+f"(acc[mt][nt][2]), "+f"(acc[mt][nt][3])
                    : "r"(afk8[0]), "r"(afk8[1]), "r"(afk8[2]), "r"(afk8[3]),
                      "r"(__float_as_uint(bv[nt].z)), "r"(__float_as_uint(bv[nt].w)));
            }
        }
    };

    auto COMPUTE2 = [&](int s) {
        const char* As = smem + s * STAGE_B;
        const char* Bs = As + HALF_B;
        COMPUTE_H(As, Bs, sw0);
        COMPUTE_H(As, Bs, sw1);
    };

    ISSUE(0, 0); ISSUE(1, 1);
    for (int kc = 0; kc < NK2 - 2; kc++) {
        asm volatile("cp.async.wait_group 1;" ::: "memory");
        __syncthreads();
        int sn = kc + 2; sn -= (sn >= NSTG) ? NSTG * (sn / NSTG) - 0 : 0;  // (kc+2)%3
        ISSUE((kc + 2) % NSTG, kc + 2);
        COMPUTE2(kc % NSTG);
    }
    asm volatile("cp.async.wait_group 1;" ::: "memory");
    __syncthreads();
    COMPUTE2((NK2 - 2) % NSTG);
    asm volatile("cp.async.wait_group 0;" ::: "memory");
    __syncthreads();
    COMPUTE2((NK2 - 1) % NSTG);
    __syncthreads();

    // ---------------- epilogue: stage tile, write direct + transposed -------
    float* stg = (float*)smem;
#pragma unroll
    for (int mt = 0; mt < 2; mt++)
#pragma unroll
        for (int nt = 0; nt < 8; nt++) {
            int il0 = wm * 32 + mt * 16 + fr;
            int il1 = il0 + 8;
            int jl  = wn * 64 + nt * 8 + fc * 2;
            stg[il0 * STR + jl]     = acc[mt][nt][0];
            stg[il0 * STR + jl + 1] = acc[mt][nt][1];
            stg[il1 * STR + jl]     = acc[mt][nt][2];
            stg[il1 * STR + jl + 1] = acc[mt][nt][3];
        }
    __syncthreads();

    // direct block: A[bm+r][bn+c]
#pragma unroll 8
    for (int e = 0; e < 64; e++) {
        int idx = tid + e * 256;
        int r = idx >> 7, c = idx & 127;
        int gi = bm + r, gj = bn + c;
        float v = stg[r * STR + c];
        if (gi == gj) v = 1.f;
        g_A[(size_t)gi * NV + gj] = v * adj[(size_t)gi * NV + gj];
    }
    // transposed block: A[bn+r][bm+c]  (off-diagonal tiles only)
    if (ti != tj) {
#pragma unroll 8
        for (int e = 0; e < 64; e++) {
            int idx = tid + e * 256;
            int r = idx >> 7, c = idx & 127;
            int gi = bn + r, gj = bm + c;
            float v = stg[c * STR + r];
            g_A[(size_t)gi * NV + gj] = v * adj[(size_t)gi * NV + gj];
        }
    }
}

// ---------------------------------------------------------------------------
// K4a: ret = bias
// ---------------------------------------------------------------------------
__global__ void k_bias(float* __restrict__ ret, const float* __restrict__ bias) {
    int idx = blockIdx.x * blockDim.x + threadIdx.x;
    ret[idx] = bias[idx & (OUT_V - 1)];
}

// ---------------------------------------------------------------------------
// K4b: ret += g_A @ g_X   (split-K=4, atomics)
// ---------------------------------------------------------------------------
constexpr int BM2 = 32, KT2 = 32, NSPLIT = 4;

__global__ void __launch_bounds__(256) k_gemm2(float* __restrict__ ret) {
    __shared__ float As2[BM2][KT2 + 1];
    __shared__ float Xs[KT2][OUT_V];
    const int bm  = blockIdx.x * BM2;
    const int kc0 = blockIdx.y * (NV / NSPLIT);
    const int kc1 = kc0 + NV / NSPLIT;
    const int tid = threadIdx.x;
    const int tx = tid & 31;
    const int ty = tid >> 5;

    float acc[4][4];
#pragma unroll
    for (int i = 0; i < 4; i++)
#pragma unroll
        for (int j = 0; j < 4; j++) acc[i][j] = 0.f;

    for (int kt = kc0; kt < kc1; kt += KT2) {
        {
            int r = tid >> 3, c4 = (tid & 7) * 4;
            float4 v = *(const float4*)&g_A[(size_t)(bm + r) * NV + kt + c4];
            As2[r][c4] = v.x; As2[r][c4 + 1] = v.y;
            As2[r][c4 + 2] = v.z; As2[r][c4 + 3] = v.w;
        }
#pragma unroll
        for (int i = 0; i < 4; i++) {
            int f = tid + i * 256;
            int r = f >> 5, c4 = (f & 31) * 4;
            *(float4*)&Xs[r][c4] = *(const float4*)&g_X[(kt + r) * OUT_V + c4];
        }
        __syncthreads();
#pragma unroll 8
        for (int k = 0; k < KT2; k++) {
            float a0 = As2[ty * 4 + 0][k];
            float a1 = As2[ty * 4 + 1][k];
            float a2 = As2[ty * 4 + 2][k];
            float a3 = As2[ty * 4 + 3][k];
            float4 b = *(const float4*)&Xs[k][tx * 4];
            acc[0][0] += a0 * b.x; acc[0][1] += a0 * b.y; acc[0][2] += a0 * b.z; acc[0][3] += a0 * b.w;
            acc[1][0] += a1 * b.x; acc[1][1] += a1 * b.y; acc[1][2] += a1 * b.z; acc[1][3] += a1 * b.w;
            acc[2][0] += a2 * b.x; acc[2][1] += a2 * b.y; acc[2][2] += a2 * b.z; acc[2][3] += a2 * b.w;
            acc[3][0] += a3 * b.x; acc[3][1] += a3 * b.y; acc[3][2] += a3 * b.z; acc[3][3] += a3 * b.w;
        }
        __syncthreads();
    }
#pragma unroll
    for (int i = 0; i < 4; i++)
#pragma unroll
        for (int j = 0; j < 4; j++)
            atomicAdd(&ret[(bm + ty * 4 + i) * OUT_V + tx * 4 + j], acc[i][j]);
}

// ---------------------------------------------------------------------------
extern "C" void kernel_launch(void* const* d_in, const int* in_sizes, int n_in,
                              void* d_out, int out_size) {
    const float* Hv   = (const float*)d_in[0];
    const float* He   = (const float*)d_in[1];
    const float* adjv = (const float*)d_in[3];
    const float* T    = (const float*)d_in[4];
    const float* W    = (const float*)d_in[5];
    const float* p    = (const float*)d_in[6];
    const float* bias = (const float*)d_in[7];
    float* out = (float*)d_out;

    cudaFuncSetAttribute(k_gemm1, cudaFuncAttributeMaxDynamicSharedMemorySize, SMEM_G1);

    k_diag<<<NE / 256, 256>>>(He, p);
    k_prep<<<(int)(((size_t)NV * NE) / 1024), 256>>>(T);
    k_hvw<<<NV, OUT_V>>>(Hv, W);
    k_gemm1<<<NPAIR, 256, SMEM_G1>>>(adjv);
    k_bias<<<NV * OUT_V / 256, 256>>>(out, bias);
    k_gemm2<<<dim3(NV / BM2, NSPLIT), 256>>>(out);

    if (out_size >= NV * OUT_V + NE * IN_E) {
        cudaMemcpyAsync(out + NV * OUT_V, He,
                        (size_t)NE * IN_E * sizeof(float),
                        cudaMemcpyDeviceToDevice, 0);
    }
}

// round 13
// speedup vs baseline: 1.4162x; 1.4162x over previous
#include <cuda_runtime.h>
#include <cstdint>

#define NV 4096
#define NE 16384
#define IN_V 128
#define OUT_V 128
#define IN_E 64

// ---------------- device global scratch (no allocation allowed) -------------
// g_Td / g_Tt hold tf32-rounded operands with each 16-float K-chunk PERMUTED
// to order [c0,c4,c8,c12, c1,c5,c9,c13, c2,c6,c10,c14, c3,c7,c11,c15] so one
// LDS.128 yields a thread's mma fragment elements for both k8 steps.
__device__ float g_A[(size_t)NV * NV];            // adjusted adjacency, 64 MB
__device__ float g_Td[(size_t)NV * NE];           // rna_tf32(T * diag), permuted
__device__ float g_Tt[(size_t)NV * NE];           // rna_tf32(T), permuted
__device__ float g_diag[NE];
__device__ float g_X[NV * OUT_V];

__device__ __forceinline__ uint32_t f2tf32(float f) {
    uint32_t u; asm("cvt.rna.tf32.f32 %0, %1;" : "=r"(u) : "f"(f)); return u;
}
__device__ __forceinline__ uint32_t s2u(const void* p) {
    uint32_t a;
    asm("{ .reg .u64 t; cvta.to.shared.u64 t, %1; cvt.u32.u64 %0, t; }" : "=r"(a) : "l"(p));
    return a;
}
__device__ __forceinline__ void cp16(uint32_t dst, const void* src) {
    asm volatile("cp.async.cg.shared.global [%0], [%1], 16;" :: "r"(dst), "l"(src) : "memory");
}

// ---------------------------------------------------------------------------
// K1: g_diag[e] = dot(H_e[e,:], p)
// ---------------------------------------------------------------------------
__global__ void k_diag(const float* __restrict__ He, const float* __restrict__ p) {
    __shared__ float sp[IN_E];
    if (threadIdx.x < IN_E) sp[threadIdx.x] = p[threadIdx.x];
    __syncthreads();
    int e = blockIdx.x * blockDim.x + threadIdx.x;
    const float* row = He + (size_t)e * IN_E;
    float acc = 0.f;
#pragma unroll
    for (int k = 0; k < IN_E; k++) acc += row[k] * sp[k];
    g_diag[e] = acc;
}

// ---------------------------------------------------------------------------
// K1b: permuted-K tf32 operands.
// ---------------------------------------------------------------------------
__global__ void __launch_bounds__(256) k_prep(const float* __restrict__ T) {
    size_t idx = (size_t)blockIdx.x * 256 + threadIdx.x;
    size_t o4 = idx * 4;
    int colin = (int)(o4 & (NE - 1));
    int g = (colin >> 2) & 3;
    size_t rowbase = o4 - colin;
    int b = (colin & ~15) + g;
    float t0 = T[rowbase + b];
    float t1 = T[rowbase + b + 4];
    float t2 = T[rowbase + b + 8];
    float t3 = T[rowbase + b + 12];
    float d0 = g_diag[b], d1 = g_diag[b + 4], d2 = g_diag[b + 8], d3 = g_diag[b + 12];
    float4 td, tt;
    td.x = __uint_as_float(f2tf32(t0 * d0)); td.y = __uint_as_float(f2tf32(t1 * d1));
    td.z = __uint_as_float(f2tf32(t2 * d2)); td.w = __uint_as_float(f2tf32(t3 * d3));
    tt.x = __uint_as_float(f2tf32(t0)); tt.y = __uint_as_float(f2tf32(t1));
    tt.z = __uint_as_float(f2tf32(t2)); tt.w = __uint_as_float(f2tf32(t3));
    *(float4*)(g_Td + o4) = td;
    *(float4*)(g_Tt + o4) = tt;
}

// ---------------------------------------------------------------------------
// K2: g_X = H_v @ weight
// ---------------------------------------------------------------------------
__global__ void k_hvw(const float* __restrict__ Hv, const float* __restrict__ W) {
    int i = blockIdx.x, j = threadIdx.x;
    const float* hr = Hv + i * IN_V;
    float acc = 0.f;
#pragma unroll 16
    for (int k = 0; k < IN_V; k++) acc += hr[k] * W[k * OUT_V + j];
    g_X[i * OUT_V + j] = acc;
}

// ---------------------------------------------------------------------------
// K3: symmetric tf32 GEMM, upper-triangle tiles.
//     32 K-floats per stage as TWO round-9-style 16-K sub-tiles (ROWB=64,
//     conflict-free). ONE barrier per 32-K. 3-stage cp.async pipeline.
// ---------------------------------------------------------------------------
constexpr int BM = 128;
constexpr int ROWB = 64;                     // bytes per smem row (16 floats)
constexpr int SUB_B = BM * ROWB;             // 8192 per sub-tile
constexpr int STAGE_B = 4 * SUB_B;           // 32768: A0 A1 B0 B1
constexpr int NSTG = 3;
constexpr int SMEM_G1 = NSTG * STAGE_B;      // 98304 (>= 66048 epilogue)
constexpr int NT1 = NV / BM;                 // 32
constexpr int NPAIR = NT1 * (NT1 + 1) / 2;   // 528
constexpr int BK2 = 32;
constexpr int NK2 = NE / BK2;                // 512
constexpr int STR = 129;                     // epilogue staging stride

__global__ void __launch_bounds__(256, 2) k_gemm1(const float* __restrict__ adj) {
    extern __shared__ char smem[];
    const uint32_t sbase = s2u(smem);

    // triangular decode: pid -> (ti, tj), ti <= tj
    int ti = 0, rem = blockIdx.x;
    while (rem >= NT1 - ti) { rem -= NT1 - ti; ti++; }
    const int tj = ti + rem;
    const int bm = ti * BM, bn = tj * BM;

    const int tid  = threadIdx.x;
    const int lane = tid & 31;
    const int warp = tid >> 5;
    const int wm = warp & 3;
    const int wn = warp >> 2;
    const int fr = lane >> 2;
    const int fc = lane & 3;
    const int swoff = (fc ^ (fr & 3)) * 16;   // constant per-thread chunk swizzle

    float acc[2][8][4];
#pragma unroll
    for (int i = 0; i < 2; i++)
#pragma unroll
        for (int j = 0; j < 8; j++)
#pragma unroll
            for (int k = 0; k < 4; k++) acc[i][j][k] = 0.f;

    // cp.async mapping (round-9 proven): row = tid>>2 (0..63, +64), chunk = tid&3
    const int lrow = tid >> 2;
    const int lch  = tid & 3;
    const float* gA = g_Td + (size_t)(bm + lrow) * NE + lch * 4;
    const float* gB = g_Tt + (size_t)(bn + lrow) * NE + lch * 4;
    const uint32_t soA  = (uint32_t)(lrow * ROWB + ((lch ^ (lrow & 3)) * 16));
    const uint32_t soA2 = soA + 64 * ROWB;

    // Stage layout: A0 @0, A1 @SUB_B, B0 @2*SUB_B, B1 @3*SUB_B
    auto ISSUE = [&](int s, int kc) {
        const uint32_t base = sbase + s * STAGE_B;
        const size_t k0 = (size_t)kc * BK2;
#pragma unroll
        for (int h = 0; h < 2; h++) {
            const uint32_t bA = base + h * SUB_B;
            const uint32_t bB = base + 2 * SUB_B + h * SUB_B;
            const size_t kk = k0 + h * 16;
            cp16(bA + soA,  gA + kk);
            cp16(bA + soA2, gA + (size_t)64 * NE + kk);
            cp16(bB + soA,  gB + kk);
            cp16(bB + soA2, gB + (size_t)64 * NE + kk);
        }
        asm volatile("cp.async.commit_group;" ::: "memory");
    };

    auto COMPUTE_H = [&](const char* As, const char* Bs) {
        float4 a0[2], a1[2];
#pragma unroll
        for (int mt = 0; mt < 2; mt++) {
            int r0 = wm * 32 + mt * 16 + fr;
            a0[mt] = *(const float4*)(As + r0 * ROWB + swoff);
            a1[mt] = *(const float4*)(As + (r0 + 8) * ROWB + swoff);
        }
        float4 bv[8];
#pragma unroll
        for (int nt = 0; nt < 8; nt++) {
            int r = wn * 64 + nt * 8 + fr;
            bv[nt] = *(const float4*)(Bs + r * ROWB + swoff);
        }
#pragma unroll
        for (int mt = 0; mt < 2; mt++) {
            uint32_t afk0[4] = { __float_as_uint(a0[mt].x), __float_as_uint(a1[mt].x),
                                 __float_as_uint(a0[mt].y), __float_as_uint(a1[mt].y) };
            uint32_t afk8[4] = { __float_as_uint(a0[mt].z), __float_as_uint(a1[mt].z),
                                 __float_as_uint(a0[mt].w), __float_as_uint(a1[mt].w) };
#pragma unroll
            for (int nt = 0; nt < 8; nt++) {
                asm volatile(
                    "mma.sync.aligned.m16n8k8.row.col.f32.tf32.tf32.f32 "
                    "{%0,%1,%2,%3}, {%4,%5,%6,%7}, {%8,%9}, {%0,%1,%2,%3};\n"
                    : "+f"(acc[mt][nt][0]), "+f"(acc[mt][nt][1]),
                      "+f"(acc[mt][nt][2]), "+f"(acc[mt][nt][3])
                    : "r"(afk0[0]), "r"(afk0[1]), "r"(afk0[2]), "r"(afk0[3]),
                      "r"(__float_as_uint(bv[nt].x)), "r"(__float_as_uint(bv[nt].y)));
                asm volatile(
                    "mma.sync.aligned.m16n8k8.row.col.f32.tf32.tf32.f32 "
                    "{%0,%1,%2,%3}, {%4,%5,%6,%7}, {%8,%9}, {%0,%1,%2,%3};\n"
                    : "+f"(acc[mt][nt][0]), "+f"(acc[mt][nt][1]),
                      "+f"(acc[mt][nt][2]), "+f"(acc[mt][nt][3])
                    : "r"(afk8[0]), "r"(afk8[1]), "r"(afk8[2]), "r"(afk8[3]),
                      "r"(__float_as_uint(bv[nt].z)), "r"(__float_as_uint(bv[nt].w)));
            }
        }
    };

    auto COMPUTE2 = [&](int s) {
        const char* st = smem + s * STAGE_B;
        COMPUTE_H(st, st + 2 * SUB_B);
        COMPUTE_H(st + SUB_B, st + 3 * SUB_B);
    };

    ISSUE(0, 0); ISSUE(1, 1);
    int s0 = 0, s2 = 2;   // rotating stage indices: current, issue-target
    for (int kc = 0; kc < NK2 - 2; kc++) {
        asm volatile("cp.async.wait_group 1;" ::: "memory");
        __syncthreads();
        ISSUE(s2, kc + 2);
        COMPUTE2(s0);
        s0 = (s0 == 2) ? 0 : s0 + 1;
        s2 = (s2 == 2) ? 0 : s2 + 1;
    }
    asm volatile("cp.async.wait_group 1;" ::: "memory");
    __syncthreads();
    COMPUTE2(s0);
    s0 = (s0 == 2) ? 0 : s0 + 1;
    asm volatile("cp.async.wait_group 0;" ::: "memory");
    __syncthreads();
    COMPUTE2(s0);
    __syncthreads();

    // ---------------- epilogue: stage tile, write direct + transposed -------
    float* stg = (float*)smem;
#pragma unroll
    for (int mt = 0; mt < 2; mt++)
#pragma unroll
        for (int nt = 0; nt < 8; nt++) {
            int il0 = wm * 32 + mt * 16 + fr;
            int il1 = il0 + 8;
            int jl  = wn * 64 + nt * 8 + fc * 2;
            stg[il0 * STR + jl]     = acc[mt][nt][0];
            stg[il0 * STR + jl + 1] = acc[mt][nt][1];
            stg[il1 * STR + jl]     = acc[mt][nt][2];
            stg[il1 * STR + jl + 1] = acc[mt][nt][3];
        }
    __syncthreads();

    // direct block: A[bm+r][bn+c]
#pragma unroll 8
    for (int e = 0; e < 64; e++) {
        int idx = tid + e * 256;
        int r = idx >> 7, c = idx & 127;
        int gi = bm + r, gj = bn + c;
        float v = stg[r * STR + c];
        if (gi == gj) v = 1.f;
        g_A[(size_t)gi * NV + gj] = v * adj[(size_t)gi * NV + gj];
    }
    // transposed block: A[bn+r][bm+c]  (off-diagonal tiles only)
    if (ti != tj) {
#pragma unroll 8
        for (int e = 0; e < 64; e++) {
            int idx = tid + e * 256;
            int r = idx >> 7, c = idx & 127;
            int gi = bn + r, gj = bm + c;
            float v = stg[c * STR + r];
            g_A[(size_t)gi * NV + gj] = v * adj[(size_t)gi * NV + gj];
        }
    }
}

// ---------------------------------------------------------------------------
// K4a: ret = bias
// ---------------------------------------------------------------------------
__global__ void k_bias(float* __restrict__ ret, const float* __restrict__ bias) {
    int idx = blockIdx.x * blockDim.x + threadIdx.x;
    ret[idx] = bias[idx & (OUT_V - 1)];
}

// ---------------------------------------------------------------------------
// K4b: ret += g_A @ g_X   (split-K=4, atomics)
// ---------------------------------------------------------------------------
constexpr int BM2 = 32, KT2 = 32, NSPLIT = 4;

__global__ void __launch_bounds__(256) k_gemm2(float* __restrict__ ret) {
    __shared__ float As2[BM2][KT2 + 1];
    __shared__ float Xs[KT2][OUT_V];
    const int bm  = blockIdx.x * BM2;
    const int kc0 = blockIdx.y * (NV / NSPLIT);
    const int kc1 = kc0 + NV / NSPLIT;
    const int tid = threadIdx.x;
    const int tx = tid & 31;
    const int ty = tid >> 5;

    float acc[4][4];
#pragma unroll
    for (int i = 0; i < 4; i++)
#pragma unroll
        for (int j = 0; j < 4; j++) acc[i][j] = 0.f;

    for (int kt = kc0; kt < kc1; kt += KT2) {
        {
            int r = tid >> 3, c4 = (tid & 7) * 4;
            float4 v = *(const float4*)&g_A[(size_t)(bm + r) * NV + kt + c4];
            As2[r][c4] = v.x; As2[r][c4 + 1] = v.y;
            As2[r][c4 + 2] = v.z; As2[r][c4 + 3] = v.w;
        }
#pragma unroll
        for (int i = 0; i < 4; i++) {
            int f = tid + i * 256;
            int r = f >> 5, c4 = (f & 31) * 4;
            *(float4*)&Xs[r][c4] = *(const float4*)&g_X[(kt + r) * OUT_V + c4];
        }
        __syncthreads();
#pragma unroll 8
        for (int k = 0; k < KT2; k++) {
            float a0 = As2[ty * 4 + 0][k];
            float a1 = As2[ty * 4 + 1][k];
            float a2 = As2[ty * 4 + 2][k];
            float a3 = As2[ty * 4 + 3][k];
            float4 b = *(const float4*)&Xs[k][tx * 4];
            acc[0][0] += a0 * b.x; acc[0][1] += a0 * b.y; acc[0][2] += a0 * b.z; acc[0][3] += a0 * b.w;
            acc[1][0] += a1 * b.x; acc[1][1] += a1 * b.y; acc[1][2] += a1 * b.z; acc[1][3] += a1 * b.w;
            acc[2][0] += a2 * b.x; acc[2][1] += a2 * b.y; acc[2][2] += a2 * b.z; acc[2][3] += a2 * b.w;
            acc[3][0] += a3 * b.x; acc[3][1] += a3 * b.y; acc[3][2] += a3 * b.z; acc[3][3] += a3 * b.w;
        }
        __syncthreads();
    }
#pragma unroll
    for (int i = 0; i < 4; i++)
#pragma unroll
        for (int j = 0; j < 4; j++)
            atomicAdd(&ret[(bm + ty * 4 + i) * OUT_V + tx * 4 + j], acc[i][j]);
}

// ---------------------------------------------------------------------------
extern "C" void kernel_launch(void* const* d_in, const int* in_sizes, int n_in,
                              void* d_out, int out_size) {
    const float* Hv   = (const float*)d_in[0];
    const float* He   = (const float*)d_in[1];
    const float* adjv = (const float*)d_in[3];
    const float* T    = (const float*)d_in[4];
    const float* W    = (const float*)d_in[5];
    const float* p    = (const float*)d_in[6];
    const float* bias = (const float*)d_in[7];
    float* out = (float*)d_out;

    cudaFuncSetAttribute(k_gemm1, cudaFuncAttributeMaxDynamicSharedMemorySize, SMEM_G1);

    k_diag<<<NE / 256, 256>>>(He, p);
    k_prep<<<(int)(((size_t)NV * NE) / 1024), 256>>>(T);
    k_hvw<<<NV, OUT_V>>>(Hv, W);
    k_gemm1<<<NPAIR, 256, SMEM_G1>>>(adjv);
    k_bias<<<NV * OUT_V / 256, 256>>>(out, bias);
    k_gemm2<<<dim3(NV / BM2, NSPLIT), 256>>>(out);

    if (out_size >= NV * OUT_V + NE * IN_E) {
        cudaMemcpyAsync(out + NV * OUT_V, He,
                        (size_t)NE * IN_E * sizeof(float),
                        cudaMemcpyDeviceToDevice, 0);
    }
}

// round 15
// speedup vs baseline: 1.4719x; 1.0394x over previous
#include <cuda_runtime.h>
#include <cstdint>

#define NV 4096
#define NE 16384
#define IN_V 128
#define OUT_V 128
#define IN_E 64

// ---------------- device global scratch (no allocation allowed) -------------
// g_Td / g_Tt hold tf32-rounded operands with each 16-float K-chunk PERMUTED
// to order [c0,c4,c8,c12, c1,c5,c9,c13, c2,c6,c10,c14, c3,c7,c11,c15] so one
// LDS.128 yields a thread's mma fragment elements for both k8 steps.
__device__ float g_A[(size_t)NV * NV];            // adjusted adjacency, 64 MB
__device__ float g_Td[(size_t)NV * NE];           // rna_tf32(T * diag), permuted
__device__ float g_Tt[(size_t)NV * NE];           // rna_tf32(T), permuted
__device__ float g_diag[NE];
__device__ float g_X[NV * OUT_V];

__device__ __forceinline__ uint32_t f2tf32(float f) {
    uint32_t u; asm("cvt.rna.tf32.f32 %0, %1;" : "=r"(u) : "f"(f)); return u;
}
__device__ __forceinline__ uint32_t s2u(const void* p) {
    uint32_t a;
    asm("{ .reg .u64 t; cvta.to.shared.u64 t, %1; cvt.u32.u64 %0, t; }" : "=r"(a) : "l"(p));
    return a;
}
__device__ __forceinline__ void cp16(uint32_t dst, const void* src) {
    asm volatile("cp.async.cg.shared.global [%0], [%1], 16;" :: "r"(dst), "l"(src) : "memory");
}

// ---------------------------------------------------------------------------
// K1: g_diag[e] = dot(H_e[e,:], p)
// ---------------------------------------------------------------------------
__global__ void k_diag(const float* __restrict__ He, const float* __restrict__ p) {
    __shared__ float sp[IN_E];
    if (threadIdx.x < IN_E) sp[threadIdx.x] = p[threadIdx.x];
    __syncthreads();
    int e = blockIdx.x * blockDim.x + threadIdx.x;
    const float* row = He + (size_t)e * IN_E;
    float acc = 0.f;
#pragma unroll
    for (int k = 0; k < IN_E; k++) acc += row[k] * sp[k];
    g_diag[e] = acc;
}

// ---------------------------------------------------------------------------
// K1b: permuted-K tf32 operands.
// ---------------------------------------------------------------------------
__global__ void __launch_bounds__(256) k_prep(const float* __restrict__ T) {
    size_t idx = (size_t)blockIdx.x * 256 + threadIdx.x;
    size_t o4 = idx * 4;
    int colin = (int)(o4 & (NE - 1));
    int g = (colin >> 2) & 3;
    size_t rowbase = o4 - colin;
    int b = (colin & ~15) + g;
    float t0 = T[rowbase + b];
    float t1 = T[rowbase + b + 4];
    float t2 = T[rowbase + b + 8];
    float t3 = T[rowbase + b + 12];
    float d0 = g_diag[b], d1 = g_diag[b + 4], d2 = g_diag[b + 8], d3 = g_diag[b + 12];
    float4 td, tt;
    td.x = __uint_as_float(f2tf32(t0 * d0)); td.y = __uint_as_float(f2tf32(t1 * d1));
    td.z = __uint_as_float(f2tf32(t2 * d2)); td.w = __uint_as_float(f2tf32(t3 * d3));
    tt.x = __uint_as_float(f2tf32(t0)); tt.y = __uint_as_float(f2tf32(t1));
    tt.z = __uint_as_float(f2tf32(t2)); tt.w = __uint_as_float(f2tf32(t3));
    *(float4*)(g_Td + o4) = td;
    *(float4*)(g_Tt + o4) = tt;
}

// ---------------------------------------------------------------------------
// K2: g_X = H_v @ weight
// ---------------------------------------------------------------------------
__global__ void k_hvw(const float* __restrict__ Hv, const float* __restrict__ W) {
    int i = blockIdx.x, j = threadIdx.x;
    const float* hr = Hv + i * IN_V;
    float acc = 0.f;
#pragma unroll 16
    for (int k = 0; k < IN_V; k++) acc += hr[k] * W[k * OUT_V + j];
    g_X[i * OUT_V + j] = acc;
}

// ---------------------------------------------------------------------------
// K3: symmetric tf32 GEMM, upper-triangle 128x128 tiles.
//     4 warps/CTA, warp tile 64x64 (2x smem reuse vs 32x64), 2 CTAs/SM,
//     ROWB=64 conflict-free layout, round-9 pipeline indices.
// ---------------------------------------------------------------------------
constexpr int BM = 128, BK = 16;
constexpr int ROWB = 64;                     // bytes per smem row (16 floats)
constexpr int HALF_B = BM * ROWB;            // 8192 per operand
constexpr int STAGE_B = 2 * HALF_B;          // 16384
constexpr int NSTG = 4;
constexpr int SMEM_G1 = 66560;               // >= max(4*16384, 128*129*4 epilogue)
constexpr int NT1 = NV / BM;                 // 32
constexpr int NPAIR = NT1 * (NT1 + 1) / 2;   // 528
constexpr int NK = NE / BK;                  // 1024
constexpr int STR = 129;                     // epilogue staging stride
constexpr int NTH = 128;                     // threads per CTA

__global__ void __launch_bounds__(NTH, 2) k_gemm1(const float* __restrict__ adj) {
    extern __shared__ char smem[];
    const uint32_t sbase = s2u(smem);

    // triangular decode: pid -> (ti, tj), ti <= tj
    int ti = 0, rem = blockIdx.x;
    while (rem >= NT1 - ti) { rem -= NT1 - ti; ti++; }
    const int tj = ti + rem;
    const int bm = ti * BM, bn = tj * BM;

    const int tid  = threadIdx.x;
    const int lane = tid & 31;
    const int warp = tid >> 5;                // 0..3
    const int wm = warp & 1;                  // 2 warps along M
    const int wn = warp >> 1;                 // 2 warps along N
    const int fr = lane >> 2;
    const int fc = lane & 3;
    const int swoff = (fc ^ (fr & 3)) * 16;   // constant per-thread chunk swizzle

    float acc[4][8][4];
#pragma unroll
    for (int i = 0; i < 4; i++)
#pragma unroll
        for (int j = 0; j < 8; j++)
#pragma unroll
            for (int k = 0; k < 4; k++) acc[i][j][k] = 0.f;

    // cp.async mapping: 128 threads; row = tid>>2 (0..31, stepped by 32), chunk = tid&3
    const int lrow = tid >> 2;                // 0..31
    const int lch  = tid & 3;
    const float* gA = g_Td + (size_t)(bm + lrow) * NE + lch * 4;
    const float* gB = g_Tt + (size_t)(bn + lrow) * NE + lch * 4;
    const uint32_t so = (uint32_t)(lrow * ROWB + ((lch ^ (lrow & 3)) * 16));

    auto ISSUE = [&](int s, int kc) {
        const uint32_t base  = sbase + s * STAGE_B;
        const uint32_t baseB = base + HALF_B;
        const size_t k0 = (size_t)kc * BK;
#pragma unroll
        for (int rb = 0; rb < 4; rb++) {
            const size_t go = (size_t)(rb * 32) * NE + k0;
            const uint32_t so2 = so + rb * 32 * ROWB;
            cp16(base + so2,  gA + go);
            cp16(baseB + so2, gB + go);
        }
        asm volatile("cp.async.commit_group;" ::: "memory");
    };

    auto COMPUTE = [&](int s) {
        const char* As = smem + s * STAGE_B;
        const char* Bs = As + HALF_B;
        float4 a0[4], a1[4];
#pragma unroll
        for (int mt = 0; mt < 4; mt++) {
            int r0 = wm * 64 + mt * 16 + fr;
            a0[mt] = *(const float4*)(As + r0 * ROWB + swoff);
            a1[mt] = *(const float4*)(As + (r0 + 8) * ROWB + swoff);
        }
        float4 bv[8];
#pragma unroll
        for (int nt = 0; nt < 8; nt++) {
            int r = wn * 64 + nt * 8 + fr;
            bv[nt] = *(const float4*)(Bs + r * ROWB + swoff);
        }
#pragma unroll
        for (int mt = 0; mt < 4; mt++) {
            uint32_t afk0[4] = { __float_as_uint(a0[mt].x), __float_as_uint(a1[mt].x),
                                 __float_as_uint(a0[mt].y), __float_as_uint(a1[mt].y) };
            uint32_t afk8[4] = { __float_as_uint(a0[mt].z), __float_as_uint(a1[mt].z),
                                 __float_as_uint(a0[mt].w), __float_as_uint(a1[mt].w) };
#pragma unroll
            for (int nt = 0; nt < 8; nt++) {
                asm volatile(
                    "mma.sync.aligned.m16n8k8.row.col.f32.tf32.tf32.f32 "
                    "{%0,%1,%2,%3}, {%4,%5,%6,%7}, {%8,%9}, {%0,%1,%2,%3};\n"
                    : "+f"(acc[mt][nt][0]), "+f"(acc[mt][nt][1]),
                      "+f"(acc[mt][nt][2]), "+f"(acc[mt][nt][3])
                    : "r"(afk0[0]), "r"(afk0[1]), "r"(afk0[2]), "r"(afk0[3]),
                      "r"(__float_as_uint(bv[nt].x)), "r"(__float_as_uint(bv[nt].y)));
                asm volatile(
                    "mma.sync.aligned.m16n8k8.row.col.f32.tf32.tf32.f32 "
                    "{%0,%1,%2,%3}, {%4,%5,%6,%7}, {%8,%9}, {%0,%1,%2,%3};\n"
                    : "+f"(acc[mt][nt][0]), "+f"(acc[mt][nt][1]),
                      "+f"(acc[mt][nt][2]), "+f"(acc[mt][nt][3])
                    : "r"(afk8[0]), "r"(afk8[1]), "r"(afk8[2]), "r"(afk8[3]),
                      "r"(__float_as_uint(bv[nt].z)), "r"(__float_as_uint(bv[nt].w)));
            }
        }
    };

    ISSUE(0, 0); ISSUE(1, 1); ISSUE(2, 2);
    for (int kc = 0; kc < NK - 3; kc++) {
        asm volatile("cp.async.wait_group 2;" ::: "memory");
        __syncthreads();
        ISSUE((kc + 3) & 3, kc + 3);
        COMPUTE(kc & 3);
    }
    asm volatile("cp.async.wait_group 1;" ::: "memory");
    __syncthreads();
    COMPUTE((NK - 3) & 3);
    asm volatile("cp.async.wait_group 0;" ::: "memory");
    __syncthreads();
    COMPUTE((NK - 2) & 3);
    COMPUTE((NK - 1) & 3);
    __syncthreads();

    // ---------------- epilogue: stage tile, write direct + transposed -------
    float* stg = (float*)smem;
#pragma unroll
    for (int mt = 0; mt < 4; mt++)
#pragma unroll
        for (int nt = 0; nt < 8; nt++) {
            int il0 = wm * 64 + mt * 16 + fr;
            int il1 = il0 + 8;
            int jl  = wn * 64 + nt * 8 + fc * 2;
            stg[il0 * STR + jl]     = acc[mt][nt][0];
            stg[il0 * STR + jl + 1] = acc[mt][nt][1];
            stg[il1 * STR + jl]     = acc[mt][nt][2];
            stg[il1 * STR + jl + 1] = acc[mt][nt][3];
        }
    __syncthreads();

    // direct block: A[bm+r][bn+c]  (128 threads: thread = column, loop rows)
#pragma unroll 4
    for (int r = 0; r < 128; r++) {
        int gi = bm + r, gj = bn + tid;
        float v = stg[r * STR + tid];
        if (gi == gj) v = 1.f;
        g_A[(size_t)gi * NV + gj] = v * adj[(size_t)gi * NV + gj];
    }
    // transposed block: A[bn+r][bm+c]  (off-diagonal tiles only)
    if (ti != tj) {
#pragma unroll 4
        for (int r = 0; r < 128; r++) {
            int gi = bn + r, gj = bm + tid;
            float v = stg[tid * STR + r];
            g_A[(size_t)gi * NV + gj] = v * adj[(size_t)gi * NV + gj];
        }
    }
}

// ---------------------------------------------------------------------------
// K4a: ret = bias
// ---------------------------------------------------------------------------
__global__ void k_bias(float* __restrict__ ret, const float* __restrict__ bias) {
    int idx = blockIdx.x * blockDim.x + threadIdx.x;
    ret[idx] = bias[idx & (OUT_V - 1)];
}

// ---------------------------------------------------------------------------
// K4b: ret += g_A @ g_X   (split-K=4, atomics)
// ---------------------------------------------------------------------------
constexpr int BM2 = 32, KT2 = 32, NSPLIT = 4;

__global__ void __launch_bounds__(256) k_gemm2(float* __restrict__ ret) {
    __shared__ float As2[BM2][KT2 + 1];
    __shared__ float Xs[KT2][OUT_V];
    const int bm  = blockIdx.x * BM2;
    const int kc0 = blockIdx.y * (NV / NSPLIT);
    const int kc1 = kc0 + NV / NSPLIT;
    const int tid = threadIdx.x;
    const int tx = tid & 31;
    const int ty = tid >> 5;

    float acc[4][4];
#pragma unroll
    for (int i = 0; i < 4; i++)
#pragma unroll
        for (int j = 0; j < 4; j++) acc[i][j] = 0.f;

    for (int kt = kc0; kt < kc1; kt += KT2) {
        {
            int r = tid >> 3, c4 = (tid & 7) * 4;
            float4 v = *(const float4*)&g_A[(size_t)(bm + r) * NV + kt + c4];
            As2[r][c4] = v.x; As2[r][c4 + 1] = v.y;
            As2[r][c4 + 2] = v.z; As2[r][c4 + 3] = v.w;
        }
#pragma unroll
        for (int i = 0; i < 4; i++) {
            int f = tid + i * 256;
            int r = f >> 5, c4 = (f & 31) * 4;
            *(float4*)&Xs[r][c4] = *(const float4*)&g_X[(kt + r) * OUT_V + c4];
        }
        __syncthreads();
#pragma unroll 8
        for (int k = 0; k < KT2; k++) {
            float a0 = As2[ty * 4 + 0][k];
            float a1 = As2[ty * 4 + 1][k];
            float a2 = As2[ty * 4 + 2][k];
            float a3 = As2[ty * 4 + 3][k];
            float4 b = *(const float4*)&Xs[k][tx * 4];
            acc[0][0] += a0 * b.x; acc[0][1] += a0 * b.y; acc[0][2] += a0 * b.z; acc[0][3] += a0 * b.w;
            acc[1][0] += a1 * b.x; acc[1][1] += a1 * b.y; acc[1][2] += a1 * b.z; acc[1][3] += a1 * b.w;
            acc[2][0] += a2 * b.x; acc[2][1] += a2 * b.y; acc[2][2] += a2 * b.z; acc[2][3] += a2 * b.w;
            acc[3][0] += a3 * b.x; acc[3][1] += a3 * b.y; acc[3][2] += a3 * b.z; acc[3][3] += a3 * b.w;
        }
        __syncthreads();
    }
#pragma unroll
    for (int i = 0; i < 4; i++)
#pragma unroll
        for (int j = 0; j < 4; j++)
            atomicAdd(&ret[(bm + ty * 4 + i) * OUT_V + tx * 4 + j], acc[i][j]);
}

// ---------------------------------------------------------------------------
extern "C" void kernel_launch(void* const* d_in, const int* in_sizes, int n_in,
                              void* d_out, int out_size) {
    const float* Hv   = (const float*)d_in[0];
    const float* He   = (const float*)d_in[1];
    const float* adjv = (const float*)d_in[3];
    const float* T    = (const float*)d_in[4];
    const float* W    = (const float*)d_in[5];
    const float* p    = (const float*)d_in[6];
    const float* bias = (const float*)d_in[7];
    float* out = (float*)d_out;

    cudaFuncSetAttribute(k_gemm1, cudaFuncAttributeMaxDynamicSharedMemorySize, SMEM_G1);

    k_diag<<<NE / 256, 256>>>(He, p);
    k_prep<<<(int)(((size_t)NV * NE) / 1024), 256>>>(T);
    k_hvw<<<NV, OUT_V>>>(Hv, W);
    k_gemm1<<<NPAIR, NTH, SMEM_G1>>>(adjv);
    k_bias<<<NV * OUT_V / 256, 256>>>(out, bias);
    k_gemm2<<<dim3(NV / BM2, NSPLIT), 256>>>(out);

    if (out_size >= NV * OUT_V + NE * IN_E) {
        cudaMemcpyAsync(out + NV * OUT_V, He,
                        (size_t)NE * IN_E * sizeof(float),
                        cudaMemcpyDeviceToDevice, 0);
    }
}

// round 16
// speedup vs baseline: 2.5556x; 1.7362x over previous
#include <cuda_runtime.h>
#include <cuda_fp16.h>
#include <cstdint>

#define NV 4096
#define NE 16384
#define IN_V 128
#define OUT_V 128
#define IN_E 64

// ---------------- device global scratch (no allocation allowed) -------------
// g_Td / g_Tt hold fp16 operands. Each 32-value K-block is PERMUTED in pairs
// so ONE LDS.128 per row yields a thread's m16n8k16 fragments for both k16
// chunks: pair order per fc-group: [k(2fc),k(2fc+8),k(16+2fc),k(24+2fc)].
__device__ float  g_A[(size_t)NV * NV];           // adjusted adjacency, 64 MB
__device__ __half g_Td[(size_t)NV * NE];          // fp16(T * diag), permuted
__device__ __half g_Tt[(size_t)NV * NE];          // fp16(T), permuted
__device__ float  g_diag[NE];
__device__ float  g_X[NV * OUT_V];

__device__ __forceinline__ uint32_t s2u(const void* p) {
    uint32_t a;
    asm("{ .reg .u64 t; cvta.to.shared.u64 t, %1; cvt.u32.u64 %0, t; }" : "=r"(a) : "l"(p));
    return a;
}
__device__ __forceinline__ void cp16(uint32_t dst, const void* src) {
    asm volatile("cp.async.cg.shared.global [%0], [%1], 16;" :: "r"(dst), "l"(src) : "memory");
}

// ---------------------------------------------------------------------------
// K1: g_diag[e] = dot(H_e[e,:], p)
// ---------------------------------------------------------------------------
__global__ void k_diag(const float* __restrict__ He, const float* __restrict__ p) {
    __shared__ float sp[IN_E];
    if (threadIdx.x < IN_E) sp[threadIdx.x] = p[threadIdx.x];
    __syncthreads();
    int e = blockIdx.x * blockDim.x + threadIdx.x;
    const float* row = He + (size_t)e * IN_E;
    float acc = 0.f;
#pragma unroll
    for (int k = 0; k < IN_E; k++) acc += row[k] * sp[k];
    g_diag[e] = acc;
}

// ---------------------------------------------------------------------------
// K1b: permuted fp16 operands. Each thread produces one 8-fp16 group (16B)
// for both g_Td and g_Tt.
// ---------------------------------------------------------------------------
__global__ void __launch_bounds__(256) k_prep(const float* __restrict__ T) {
    size_t idx = (size_t)blockIdx.x * 256 + threadIdx.x;
    size_t o8 = idx * 8;                       // fp16 output index
    int col = (int)(o8 & (NE - 1));            // multiple of 8
    size_t rowbase = o8 - col;
    int k32 = col & ~31;
    int fcg = (col >> 3) & 3;                  // fc group 0..3
    int k0 = k32 + 2 * fcg;
    const float* Tr = T + rowbase;
    float2 t0 = *(const float2*)(Tr + k0);
    float2 t1 = *(const float2*)(Tr + k0 + 8);
    float2 t2 = *(const float2*)(Tr + k0 + 16);
    float2 t3 = *(const float2*)(Tr + k0 + 24);
    float2 d0 = *(const float2*)(g_diag + k0);
    float2 d1 = *(const float2*)(g_diag + k0 + 8);
    float2 d2 = *(const float2*)(g_diag + k0 + 16);
    float2 d3 = *(const float2*)(g_diag + k0 + 24);
    __half2 td[4], tt[4];
    td[0] = __floats2half2_rn(t0.x * d0.x, t0.y * d0.y);
    td[1] = __floats2half2_rn(t1.x * d1.x, t1.y * d1.y);
    td[2] = __floats2half2_rn(t2.x * d2.x, t2.y * d2.y);
    td[3] = __floats2half2_rn(t3.x * d3.x, t3.y * d3.y);
    tt[0] = __floats2half2_rn(t0.x, t0.y);
    tt[1] = __floats2half2_rn(t1.x, t1.y);
    tt[2] = __floats2half2_rn(t2.x, t2.y);
    tt[3] = __floats2half2_rn(t3.x, t3.y);
    *(uint4*)(g_Td + rowbase + col) = *(const uint4*)td;
    *(uint4*)(g_Tt + rowbase + col) = *(const uint4*)tt;
}

// ---------------------------------------------------------------------------
// K2: g_X = H_v @ weight
// ---------------------------------------------------------------------------
__global__ void k_hvw(const float* __restrict__ Hv, const float* __restrict__ W) {
    int i = blockIdx.x, j = threadIdx.x;
    const float* hr = Hv + i * IN_V;
    float acc = 0.f;
#pragma unroll 16
    for (int k = 0; k < IN_V; k++) acc += hr[k] * W[k * OUT_V + j];
    g_X[i * OUT_V + j] = acc;
}

// ---------------------------------------------------------------------------
// K3: symmetric fp16 GEMM (fp32 accum), upper-triangle 128x128 tiles.
//     m16n8k16 mma, K32 per stage, 4 warps x 64x64 tiles, 2 CTAs/SM,
//     ROWB=64 conflict-free layout.
// ---------------------------------------------------------------------------
constexpr int BM = 128;
constexpr int BK = 32;                       // K fp16 values per stage
constexpr int ROWB = 64;                     // bytes per smem row (32 fp16)
constexpr int HALF_B = BM * ROWB;            // 8192 per operand
constexpr int STAGE_B = 2 * HALF_B;          // 16384
constexpr int NSTG = 4;
constexpr int SMEM_G1 = 66560;               // >= max(4*16384, 128*129*4 epilogue)
constexpr int NT1 = NV / BM;                 // 32
constexpr int NPAIR = NT1 * (NT1 + 1) / 2;   // 528
constexpr int NK = NE / BK;                  // 512
constexpr int STR = 129;                     // epilogue staging stride
constexpr int NTH = 128;                     // threads per CTA

__global__ void __launch_bounds__(NTH, 2) k_gemm1(const float* __restrict__ adj) {
    extern __shared__ char smem[];
    const uint32_t sbase = s2u(smem);

    // triangular decode: pid -> (ti, tj), ti <= tj
    int ti = 0, rem = blockIdx.x;
    while (rem >= NT1 - ti) { rem -= NT1 - ti; ti++; }
    const int tj = ti + rem;
    const int bm = ti * BM, bn = tj * BM;

    const int tid  = threadIdx.x;
    const int lane = tid & 31;
    const int warp = tid >> 5;                // 0..3
    const int wm = warp & 1;                  // 2 warps along M
    const int wn = warp >> 1;                 // 2 warps along N
    const int fr = lane >> 2;
    const int fc = lane & 3;
    const int swoff = (fc ^ (fr & 3)) * 16;   // constant per-thread chunk swizzle

    float acc[4][8][4];
#pragma unroll
    for (int i = 0; i < 4; i++)
#pragma unroll
        for (int j = 0; j < 8; j++)
#pragma unroll
            for (int k = 0; k < 4; k++) acc[i][j][k] = 0.f;

    // cp.async mapping: 128 threads; row = tid>>2 (0..31, stepped by 32), chunk = tid&3
    const int lrow = tid >> 2;
    const int lch  = tid & 3;
    const __half* gA = g_Td + (size_t)(bm + lrow) * NE + lch * 8;
    const __half* gB = g_Tt + (size_t)(bn + lrow) * NE + lch * 8;
    const uint32_t so = (uint32_t)(lrow * ROWB + ((lch ^ (lrow & 3)) * 16));

    auto ISSUE = [&](int s, int kc) {
        const uint32_t base  = sbase + s * STAGE_B;
        const uint32_t baseB = base + HALF_B;
        const size_t k0 = (size_t)kc * BK;
#pragma unroll
        for (int rb = 0; rb < 4; rb++) {
            const size_t go = (size_t)(rb * 32) * NE + k0;
            const uint32_t so2 = so + rb * 32 * ROWB;
            cp16(base + so2,  gA + go);
            cp16(baseB + so2, gB + go);
        }
        asm volatile("cp.async.commit_group;" ::: "memory");
    };

    auto COMPUTE = [&](int s) {
        const char* As = smem + s * STAGE_B;
        const char* Bs = As + HALF_B;
        // A fragments: 4 m-tiles x 2 rows, one LDS.128 each (covers both k16)
        uint4 av0[4], av1[4];
#pragma unroll
        for (int mt = 0; mt < 4; mt++) {
            int r0 = wm * 64 + mt * 16 + fr;
            av0[mt] = *(const uint4*)(As + r0 * ROWB + swoff);
            av1[mt] = *(const uint4*)(As + (r0 + 8) * ROWB + swoff);
        }
        // B fragments: 8 n-tiles, one LDS.128 each (covers both k16)
        uint4 bv[8];
#pragma unroll
        for (int nt = 0; nt < 8; nt++) {
            int r = wn * 64 + nt * 8 + fr;
            bv[nt] = *(const uint4*)(Bs + r * ROWB + swoff);
        }
#pragma unroll
        for (int mt = 0; mt < 4; mt++) {
#pragma unroll
            for (int nt = 0; nt < 8; nt++) {
                // chunk0: k = [0,16)
                asm volatile(
                    "mma.sync.aligned.m16n8k16.row.col.f32.f16.f16.f32 "
                    "{%0,%1,%2,%3}, {%4,%5,%6,%7}, {%8,%9}, {%0,%1,%2,%3};\n"
                    : "+f"(acc[mt][nt][0]), "+f"(acc[mt][nt][1]),
                      "+f"(acc[mt][nt][2]), "+f"(acc[mt][nt][3])
                    : "r"(av0[mt].x), "r"(av1[mt].x), "r"(av0[mt].y), "r"(av1[mt].y),
                      "r"(bv[nt].x), "r"(bv[nt].y));
                // chunk1: k = [16,32)
                asm volatile(
                    "mma.sync.aligned.m16n8k16.row.col.f32.f16.f16.f32 "
                    "{%0,%1,%2,%3}, {%4,%5,%6,%7}, {%8,%9}, {%0,%1,%2,%3};\n"
                    : "+f"(acc[mt][nt][0]), "+f"(acc[mt][nt][1]),
                      "+f"(acc[mt][nt][2]), "+f"(acc[mt][nt][3])
                    : "r"(av0[mt].z), "r"(av1[mt].z), "r"(av0[mt].w), "r"(av1[mt].w),
                      "r"(bv[nt].z), "r"(bv[nt].w));
            }
        }
    };

    ISSUE(0, 0); ISSUE(1, 1); ISSUE(2, 2);
    for (int kc = 0; kc < NK - 3; kc++) {
        asm volatile("cp.async.wait_group 2;" ::: "memory");
        __syncthreads();
        ISSUE((kc + 3) & 3, kc + 3);
        COMPUTE(kc & 3);
    }
    asm volatile("cp.async.wait_group 1;" ::: "memory");
    __syncthreads();
    COMPUTE((NK - 3) & 3);
    asm volatile("cp.async.wait_group 0;" ::: "memory");
    __syncthreads();
    COMPUTE((NK - 2) & 3);
    COMPUTE((NK - 1) & 3);
    __syncthreads();

    // ---------------- epilogue: stage tile, write direct + transposed -------
    float* stg = (float*)smem;
#pragma unroll
    for (int mt = 0; mt < 4; mt++)
#pragma unroll
        for (int nt = 0; nt < 8; nt++) {
            int il0 = wm * 64 + mt * 16 + fr;
            int il1 = il0 + 8;
            int jl  = wn * 64 + nt * 8 + fc * 2;
            stg[il0 * STR + jl]     = acc[mt][nt][0];
            stg[il0 * STR + jl + 1] = acc[mt][nt][1];
            stg[il1 * STR + jl]     = acc[mt][nt][2];
            stg[il1 * STR + jl + 1] = acc[mt][nt][3];
        }
    __syncthreads();

    // direct block: A[bm+r][bn+c]  (128 threads: thread = column, loop rows)
#pragma unroll 4
    for (int r = 0; r < 128; r++) {
        int gi = bm + r, gj = bn + tid;
        float v = stg[r * STR + tid];
        if (gi == gj) v = 1.f;
        g_A[(size_t)gi * NV + gj] = v * adj[(size_t)gi * NV + gj];
    }
    // transposed block: A[bn+r][bm+c]  (off-diagonal tiles only)
    if (ti != tj) {
#pragma unroll 4
        for (int r = 0; r < 128; r++) {
            int gi = bn + r, gj = bm + tid;
            float v = stg[tid * STR + r];
            g_A[(size_t)gi * NV + gj] = v * adj[(size_t)gi * NV + gj];
        }
    }
}

// ---------------------------------------------------------------------------
// K4a: ret = bias
// ---------------------------------------------------------------------------
__global__ void k_bias(float* __restrict__ ret, const float* __restrict__ bias) {
    int idx = blockIdx.x * blockDim.x + threadIdx.x;
    ret[idx] = bias[idx & (OUT_V - 1)];
}

// ---------------------------------------------------------------------------
// K4b: ret += g_A @ g_X   (split-K=4, atomics)
// ---------------------------------------------------------------------------
constexpr int BM2 = 32, KT2 = 32, NSPLIT = 4;

__global__ void __launch_bounds__(256) k_gemm2(float* __restrict__ ret) {
    __shared__ float As2[BM2][KT2 + 1];
    __shared__ float Xs[KT2][OUT_V];
    const int bm  = blockIdx.x * BM2;
    const int kc0 = blockIdx.y * (NV / NSPLIT);
    const int kc1 = kc0 + NV / NSPLIT;
    const int tid = threadIdx.x;
    const int tx = tid & 31;
    const int ty = tid >> 5;

    float acc[4][4];
#pragma unroll
    for (int i = 0; i < 4; i++)
#pragma unroll
        for (int j = 0; j < 4; j++) acc[i][j] = 0.f;

    for (int kt = kc0; kt < kc1; kt += KT2) {
        {
            int r = tid >> 3, c4 = (tid & 7) * 4;
            float4 v = *(const float4*)&g_A[(size_t)(bm + r) * NV + kt + c4];
            As2[r][c4] = v.x; As2[r][c4 + 1] = v.y;
            As2[r][c4 + 2] = v.z; As2[r][c4 + 3] = v.w;
        }
#pragma unroll
        for (int i = 0; i < 4; i++) {
            int f = tid + i * 256;
            int r = f >> 5, c4 = (f & 31) * 4;
            *(float4*)&Xs[r][c4] = *(const float4*)&g_X[(kt + r) * OUT_V + c4];
        }
        __syncthreads();
#pragma unroll 8
        for (int k = 0; k < KT2; k++) {
            float a0 = As2[ty * 4 + 0][k];
            float a1 = As2[ty * 4 + 1][k];
            float a2 = As2[ty * 4 + 2][k];
            float a3 = As2[ty * 4 + 3][k];
            float4 b = *(const float4*)&Xs[k][tx * 4];
            acc[0][0] += a0 * b.x; acc[0][1] += a0 * b.y; acc[0][2] += a0 * b.z; acc[0][3] += a0 * b.w;
            acc[1][0] += a1 * b.x; acc[1][1] += a1 * b.y; acc[1][2] += a1 * b.z; acc[1][3] += a1 * b.w;
            acc[2][0] += a2 * b.x; acc[2][1] += a2 * b.y; acc[2][2] += a2 * b.z; acc[2][3] += a2 * b.w;
            acc[3][0] += a3 * b.x; acc[3][1] += a3 * b.y; acc[3][2] += a3 * b.z; acc[3][3] += a3 * b.w;
        }
        __syncthreads();
    }
#pragma unroll
    for (int i = 0; i < 4; i++)
#pragma unroll
        for (int j = 0; j < 4; j++)
            atomicAdd(&ret[(bm + ty * 4 + i) * OUT_V + tx * 4 + j], acc[i][j]);
}

// ---------------------------------------------------------------------------
extern "C" void kernel_launch(void* const* d_in, const int* in_sizes, int n_in,
                              void* d_out, int out_size) {
    const float* Hv   = (const float*)d_in[0];
    const float* He   = (const float*)d_in[1];
    const float* adjv = (const float*)d_in[3];
    const float* T    = (const float*)d_in[4];
    const float* W    = (const float*)d_in[5];
    const float* p    = (const float*)d_in[6];
    const float* bias = (const float*)d_in[7];
    float* out = (float*)d_out;

    cudaFuncSetAttribute(k_gemm1, cudaFuncAttributeMaxDynamicSharedMemorySize, SMEM_G1);

    k_diag<<<NE / 256, 256>>>(He, p);
    k_prep<<<(int)(((size_t)NV * NE) / 8 / 256), 256>>>(T);
    k_hvw<<<NV, OUT_V>>>(Hv, W);
    k_gemm1<<<NPAIR, NTH, SMEM_G1>>>(adjv);
    k_bias<<<NV * OUT_V / 256, 256>>>(out, bias);
    k_gemm2<<<dim3(NV / BM2, NSPLIT), 256>>>(out);

    if (out_size >= NV * OUT_V + NE * IN_E) {
        cudaMemcpyAsync(out + NV * OUT_V, He,
                        (size_t)NE * IN_E * sizeof(float),
                        cudaMemcpyDeviceToDevice, 0);
    }
}

// round 17
// speedup vs baseline: 2.8759x; 1.1253x over previous
#include <cuda_runtime.h>
#include <cuda_fp16.h>
#include <cstdint>

#define NV 4096
#define NE 16384
#define IN_V 128
#define OUT_V 128
#define IN_E 64

// ---------------- device global scratch (no allocation allowed) -------------
// All fp16 operand arrays use the permuted K layout: within each 32-value
// K-block, orig position r maps to perm32(r) = ((r&6)>>1)*8 + (r>>3)*2 + (r&1),
// so ONE LDS.128 per row yields a thread's m16n8k16 fragments for both k16
// chunks of a K32 window.
__device__ __half g_Td[(size_t)NV * NE];          // fp16(T * diag), permuted
__device__ __half g_Tt[(size_t)NV * NE];          // fp16(T), permuted
__device__ __half g_Ah[(size_t)NV * NV];          // fp16 adjusted adjacency, permuted-K
__device__ __half g_Xht[(size_t)OUT_V * NV];      // fp16 (H_v@W)^T, permuted-K
__device__ float  g_diag[NE];

__device__ __forceinline__ int perm32(int r) {
    return ((r & 6) >> 1) * 8 + (r >> 3) * 2 + (r & 1);
}
__device__ __forceinline__ uint32_t s2u(const void* p) {
    uint32_t a;
    asm("{ .reg .u64 t; cvta.to.shared.u64 t, %1; cvt.u32.u64 %0, t; }" : "=r"(a) : "l"(p));
    return a;
}
__device__ __forceinline__ void cp16(uint32_t dst, const void* src) {
    asm volatile("cp.async.cg.shared.global [%0], [%1], 16;" :: "r"(dst), "l"(src) : "memory");
}

// ---------------------------------------------------------------------------
// K1: g_diag[e] = dot(H_e[e,:], p)
// ---------------------------------------------------------------------------
__global__ void k_diag(const float* __restrict__ He, const float* __restrict__ p) {
    __shared__ float sp[IN_E];
    if (threadIdx.x < IN_E) sp[threadIdx.x] = p[threadIdx.x];
    __syncthreads();
    int e = blockIdx.x * blockDim.x + threadIdx.x;
    const float* row = He + (size_t)e * IN_E;
    float acc = 0.f;
#pragma unroll
    for (int k = 0; k < IN_E; k++) acc += row[k] * sp[k];
    g_diag[e] = acc;
}

// ---------------------------------------------------------------------------
// K1b: permuted fp16 operands. Each thread produces one 8-fp16 group (16B)
// for both g_Td and g_Tt.
// ---------------------------------------------------------------------------
__global__ void __launch_bounds__(256) k_prep(const float* __restrict__ T) {
    size_t idx = (size_t)blockIdx.x * 256 + threadIdx.x;
    size_t o8 = idx * 8;                       // fp16 output index
    int col = (int)(o8 & (NE - 1));            // multiple of 8
    size_t rowbase = o8 - col;
    int k32 = col & ~31;
    int fcg = (col >> 3) & 3;                  // fc group 0..3
    int k0 = k32 + 2 * fcg;
    const float* Tr = T + rowbase;
    float2 t0 = *(const float2*)(Tr + k0);
    float2 t1 = *(const float2*)(Tr + k0 + 8);
    float2 t2 = *(const float2*)(Tr + k0 + 16);
    float2 t3 = *(const float2*)(Tr + k0 + 24);
    float2 d0 = *(const float2*)(g_diag + k0);
    float2 d1 = *(const float2*)(g_diag + k0 + 8);
    float2 d2 = *(const float2*)(g_diag + k0 + 16);
    float2 d3 = *(const float2*)(g_diag + k0 + 24);
    __half2 td[4], tt[4];
    td[0] = __floats2half2_rn(t0.x * d0.x, t0.y * d0.y);
    td[1] = __floats2half2_rn(t1.x * d1.x, t1.y * d1.y);
    td[2] = __floats2half2_rn(t2.x * d2.x, t2.y * d2.y);
    td[3] = __floats2half2_rn(t3.x * d3.x, t3.y * d3.y);
    tt[0] = __floats2half2_rn(t0.x, t0.y);
    tt[1] = __floats2half2_rn(t1.x, t1.y);
    tt[2] = __floats2half2_rn(t2.x, t2.y);
    tt[3] = __floats2half2_rn(t3.x, t3.y);
    *(uint4*)(g_Td + rowbase + col) = *(const uint4*)td;
    *(uint4*)(g_Tt + rowbase + col) = *(const uint4*)tt;
}

// ---------------------------------------------------------------------------
// K2: g_Xht[j][perm(i)] = fp16(dot(H_v[i,:], W[:,j]))   (transposed, permuted)
// ---------------------------------------------------------------------------
__global__ void k_hvw(const float* __restrict__ Hv, const float* __restrict__ W) {
    int i = blockIdx.x, j = threadIdx.x;
    const float* hr = Hv + i * IN_V;
    float acc = 0.f;
#pragma unroll 16
    for (int k = 0; k < IN_V; k++) acc += hr[k] * W[k * OUT_V + j];
    int pi = (i & ~31) | perm32(i & 31);
    g_Xht[(size_t)j * NV + pi] = __float2half(acc);
}

// ---------------------------------------------------------------------------
// Shared GEMM machinery (fp16 m16n8k16, 4 warps x 64x64, ROWB=64 layout)
// ---------------------------------------------------------------------------
constexpr int BM = 128;
constexpr int BK = 32;                       // K fp16 values per stage
constexpr int ROWB = 64;                     // bytes per smem row (32 fp16)
constexpr int HALF_B = BM * ROWB;            // 8192 per operand
constexpr int STAGE_B = 2 * HALF_B;          // 16384
constexpr int SMEM_G1 = 66560;               // >= max(4*16384, 128*129*4 epilogue)
constexpr int SMEM_G2 = 65536;
constexpr int NT1 = NV / BM;                 // 32
constexpr int NPAIR = NT1 * (NT1 + 1) / 2;   // 528
constexpr int NK1 = NE / BK;                 // 512
constexpr int STR = 129;                     // epilogue staging stride
constexpr int NTH = 128;                     // threads per CTA
constexpr int KSPLIT2 = 8;
constexpr int NK2 = (NV / KSPLIT2) / BK;     // 16

struct Frag { float a[4][8][4]; };

// ---------------------------------------------------------------------------
// K3: symmetric fp16 GEMM (fp32 accum), upper-triangle 128x128 tiles.
//     Epilogue: diag->1, * adj_v, write fp16 permuted-K g_Ah (both blocks).
// ---------------------------------------------------------------------------
__global__ void __launch_bounds__(NTH, 2) k_gemm1(const float* __restrict__ adj) {
    extern __shared__ char smem[];
    const uint32_t sbase = s2u(smem);

    int ti = 0, rem = blockIdx.x;
    while (rem >= NT1 - ti) { rem -= NT1 - ti; ti++; }
    const int tj = ti + rem;
    const int bm = ti * BM, bn = tj * BM;

    const int tid  = threadIdx.x;
    const int lane = tid & 31;
    const int warp = tid >> 5;
    const int wm = warp & 1;
    const int wn = warp >> 1;
    const int fr = lane >> 2;
    const int fc = lane & 3;
    const int swoff = (fc ^ (fr & 3)) * 16;

    float acc[4][8][4];
#pragma unroll
    for (int i = 0; i < 4; i++)
#pragma unroll
        for (int j = 0; j < 8; j++)
#pragma unroll
            for (int k = 0; k < 4; k++) acc[i][j][k] = 0.f;

    const int lrow = tid >> 2;
    const int lch  = tid & 3;
    const __half* gA = g_Td + (size_t)(bm + lrow) * NE + lch * 8;
    const __half* gB = g_Tt + (size_t)(bn + lrow) * NE + lch * 8;
    const uint32_t so = (uint32_t)(lrow * ROWB + ((lch ^ (lrow & 3)) * 16));

    auto ISSUE = [&](int s, int kc) {
        const uint32_t base  = sbase + s * STAGE_B;
        const uint32_t baseB = base + HALF_B;
        const size_t k0 = (size_t)kc * BK;
#pragma unroll
        for (int rb = 0; rb < 4; rb++) {
            const size_t go = (size_t)(rb * 32) * NE + k0;
            const uint32_t so2 = so + rb * 32 * ROWB;
            cp16(base + so2,  gA + go);
            cp16(baseB + so2, gB + go);
        }
        asm volatile("cp.async.commit_group;" ::: "memory");
    };

    auto COMPUTE = [&](int s) {
        const char* As = smem + s * STAGE_B;
        const char* Bs = As + HALF_B;
        uint4 av0[4], av1[4];
#pragma unroll
        for (int mt = 0; mt < 4; mt++) {
            int r0 = wm * 64 + mt * 16 + fr;
            av0[mt] = *(const uint4*)(As + r0 * ROWB + swoff);
            av1[mt] = *(const uint4*)(As + (r0 + 8) * ROWB + swoff);
        }
        uint4 bv[8];
#pragma unroll
        for (int nt = 0; nt < 8; nt++) {
            int r = wn * 64 + nt * 8 + fr;
            bv[nt] = *(const uint4*)(Bs + r * ROWB + swoff);
        }
#pragma unroll
        for (int mt = 0; mt < 4; mt++) {
#pragma unroll
            for (int nt = 0; nt < 8; nt++) {
                asm volatile(
                    "mma.sync.aligned.m16n8k16.row.col.f32.f16.f16.f32 "
                    "{%0,%1,%2,%3}, {%4,%5,%6,%7}, {%8,%9}, {%0,%1,%2,%3};\n"
                    : "+f"(acc[mt][nt][0]), "+f"(acc[mt][nt][1]),
                      "+f"(acc[mt][nt][2]), "+f"(acc[mt][nt][3])
                    : "r"(av0[mt].x), "r"(av1[mt].x), "r"(av0[mt].y), "r"(av1[mt].y),
                      "r"(bv[nt].x), "r"(bv[nt].y));
                asm volatile(
                    "mma.sync.aligned.m16n8k16.row.col.f32.f16.f16.f32 "
                    "{%0,%1,%2,%3}, {%4,%5,%6,%7}, {%8,%9}, {%0,%1,%2,%3};\n"
                    : "+f"(acc[mt][nt][0]), "+f"(acc[mt][nt][1]),
                      "+f"(acc[mt][nt][2]), "+f"(acc[mt][nt][3])
                    : "r"(av0[mt].z), "r"(av1[mt].z), "r"(av0[mt].w), "r"(av1[mt].w),
                      "r"(bv[nt].z), "r"(bv[nt].w));
            }
        }
    };

    ISSUE(0, 0); ISSUE(1, 1); ISSUE(2, 2);
    for (int kc = 0; kc < NK1 - 3; kc++) {
        asm volatile("cp.async.wait_group 2;" ::: "memory");
        __syncthreads();
        ISSUE((kc + 3) & 3, kc + 3);
        COMPUTE(kc & 3);
    }
    asm volatile("cp.async.wait_group 1;" ::: "memory");
    __syncthreads();
    COMPUTE((NK1 - 3) & 3);
    asm volatile("cp.async.wait_group 0;" ::: "memory");
    __syncthreads();
    COMPUTE((NK1 - 2) & 3);
    COMPUTE((NK1 - 1) & 3);
    __syncthreads();

    // ---------------- epilogue: stage tile, write fp16 permuted g_Ah --------
    float* stg = (float*)smem;
#pragma unroll
    for (int mt = 0; mt < 4; mt++)
#pragma unroll
        for (int nt = 0; nt < 8; nt++) {
            int il0 = wm * 64 + mt * 16 + fr;
            int il1 = il0 + 8;
            int jl  = wn * 64 + nt * 8 + fc * 2;
            stg[il0 * STR + jl]     = acc[mt][nt][0];
            stg[il0 * STR + jl + 1] = acc[mt][nt][1];
            stg[il1 * STR + jl]     = acc[mt][nt][2];
            stg[il1 * STR + jl + 1] = acc[mt][nt][3];
        }
    __syncthreads();

    const int ptid = (tid & ~31) | perm32(tid & 31);   // permuted column slot
    // direct block: Ah[bm+r][perm(bn+tid)]
#pragma unroll 4
    for (int r = 0; r < 128; r++) {
        int gi = bm + r;
        float v = stg[r * STR + tid];
        if (gi == bn + tid) v = 1.f;
        v *= adj[(size_t)gi * NV + bn + tid];
        g_Ah[(size_t)gi * NV + bn + ptid] = __float2half(v);
    }
    // transposed block: Ah[bn+r][perm(bm+tid)]  (off-diagonal tiles only)
    if (ti != tj) {
#pragma unroll 4
        for (int r = 0; r < 128; r++) {
            int gi = bn + r;
            float v = stg[tid * STR + r];
            v *= adj[(size_t)gi * NV + bm + tid];
            g_Ah[(size_t)gi * NV + bm + ptid] = __float2half(v);
        }
    }
}

// ---------------------------------------------------------------------------
// K4a: ret = bias
// ---------------------------------------------------------------------------
__global__ void k_bias(float* __restrict__ ret, const float* __restrict__ bias) {
    int idx = blockIdx.x * blockDim.x + threadIdx.x;
    ret[idx] = bias[idx & (OUT_V - 1)];
}

// ---------------------------------------------------------------------------
// K4b: ret += g_Ah @ g_Xht^T  (fp16 tensor, split-K=8, fp32 atomics)
//      Same verified mainloop/fragment layout as k_gemm1; NK=16 per CTA.
// ---------------------------------------------------------------------------
__global__ void __launch_bounds__(NTH, 2) k_gemm2h(float* __restrict__ ret) {
    extern __shared__ char smem[];
    const uint32_t sbase = s2u(smem);

    const int bm = blockIdx.x * BM;
    const int kbase = blockIdx.y * (NV / KSPLIT2);

    const int tid  = threadIdx.x;
    const int lane = tid & 31;
    const int warp = tid >> 5;
    const int wm = warp & 1;
    const int wn = warp >> 1;
    const int fr = lane >> 2;
    const int fc = lane & 3;
    const int swoff = (fc ^ (fr & 3)) * 16;

    float acc[4][8][4];
#pragma unroll
    for (int i = 0; i < 4; i++)
#pragma unroll
        for (int j = 0; j < 8; j++)
#pragma unroll
            for (int k = 0; k < 4; k++) acc[i][j][k] = 0.f;

    const int lrow = tid >> 2;
    const int lch  = tid & 3;
    const __half* gA = g_Ah + (size_t)(bm + lrow) * NV + kbase + lch * 8;
    const __half* gB = g_Xht + (size_t)lrow * NV + kbase + lch * 8;
    const uint32_t so = (uint32_t)(lrow * ROWB + ((lch ^ (lrow & 3)) * 16));

    auto ISSUE = [&](int s, int kc) {
        const uint32_t base  = sbase + s * STAGE_B;
        const uint32_t baseB = base + HALF_B;
        const size_t k0 = (size_t)kc * BK;
#pragma unroll
        for (int rb = 0; rb < 4; rb++) {
            const size_t go = (size_t)(rb * 32) * NV + k0;
            const uint32_t so2 = so + rb * 32 * ROWB;
            cp16(base + so2,  gA + go);
            cp16(baseB + so2, gB + go);
        }
        asm volatile("cp.async.commit_group;" ::: "memory");
    };

    auto COMPUTE = [&](int s) {
        const char* As = smem + s * STAGE_B;
        const char* Bs = As + HALF_B;
        uint4 av0[4], av1[4];
#pragma unroll
        for (int mt = 0; mt < 4; mt++) {
            int r0 = wm * 64 + mt * 16 + fr;
            av0[mt] = *(const uint4*)(As + r0 * ROWB + swoff);
            av1[mt] = *(const uint4*)(As + (r0 + 8) * ROWB + swoff);
        }
        uint4 bv[8];
#pragma unroll
        for (int nt = 0; nt < 8; nt++) {
            int r = wn * 64 + nt * 8 + fr;
            bv[nt] = *(const uint4*)(Bs + r * ROWB + swoff);
        }
#pragma unroll
        for (int mt = 0; mt < 4; mt++) {
#pragma unroll
            for (int nt = 0; nt < 8; nt++) {
                asm volatile(
                    "mma.sync.aligned.m16n8k16.row.col.f32.f16.f16.f32 "
                    "{%0,%1,%2,%3}, {%4,%5,%6,%7}, {%8,%9}, {%0,%1,%2,%3};\n"
                    : "+f"(acc[mt][nt][0]), "+f"(acc[mt][nt][1]),
                      "+f"(acc[mt][nt][2]), "+f"(acc[mt][nt][3])
                    : "r"(av0[mt].x), "r"(av1[mt].x), "r"(av0[mt].y), "r"(av1[mt].y),
                      "r"(bv[nt].x), "r"(bv[nt].y));
                asm volatile(
                    "mma.sync.aligned.m16n8k16.row.col.f32.f16.f16.f32 "
                    "{%0,%1,%2,%3}, {%4,%5,%6,%7}, {%8,%9}, {%0,%1,%2,%3};\n"
                    : "+f"(acc[mt][nt][0]), "+f"(acc[mt][nt][1]),
                      "+f"(acc[mt][nt][2]), "+f"(acc[mt][nt][3])
                    : "r"(av0[mt].z), "r"(av1[mt].z), "r"(av0[mt].w), "r"(av1[mt].w),
                      "r"(bv[nt].z), "r"(bv[nt].w));
            }
        }
    };

    ISSUE(0, 0); ISSUE(1, 1); ISSUE(2, 2);
    for (int kc = 0; kc < NK2 - 3; kc++) {
        asm volatile("cp.async.wait_group 2;" ::: "memory");
        __syncthreads();
        ISSUE((kc + 3) & 3, kc + 3);
        COMPUTE(kc & 3);
    }
    asm volatile("cp.async.wait_group 1;" ::: "memory");
    __syncthreads();
    COMPUTE((NK2 - 3) & 3);
    asm volatile("cp.async.wait_group 0;" ::: "memory");
    __syncthreads();
    COMPUTE((NK2 - 2) & 3);
    COMPUTE((NK2 - 1) & 3);

    // epilogue: accumulate partial into ret
#pragma unroll
    for (int mt = 0; mt < 4; mt++) {
#pragma unroll
        for (int nt = 0; nt < 8; nt++) {
            int gi0 = bm + wm * 64 + mt * 16 + fr;
            int gi1 = gi0 + 8;
            int jl  = wn * 64 + nt * 8 + fc * 2;
            atomicAdd(&ret[gi0 * OUT_V + jl],     acc[mt][nt][0]);
            atomicAdd(&ret[gi0 * OUT_V + jl + 1], acc[mt][nt][1]);
            atomicAdd(&ret[gi1 * OUT_V + jl],     acc[mt][nt][2]);
            atomicAdd(&ret[gi1 * OUT_V + jl + 1], acc[mt][nt][3]);
        }
    }
}

// ---------------------------------------------------------------------------
extern "C" void kernel_launch(void* const* d_in, const int* in_sizes, int n_in,
                              void* d_out, int out_size) {
    const float* Hv   = (const float*)d_in[0];
    const float* He   = (const float*)d_in[1];
    const float* adjv = (const float*)d_in[3];
    const float* T    = (const float*)d_in[4];
    const float* W    = (const float*)d_in[5];
    const float* p    = (const float*)d_in[6];
    const float* bias = (const float*)d_in[7];
    float* out = (float*)d_out;

    cudaFuncSetAttribute(k_gemm1, cudaFuncAttributeMaxDynamicSharedMemorySize, SMEM_G1);
    cudaFuncSetAttribute(k_gemm2h, cudaFuncAttributeMaxDynamicSharedMemorySize, SMEM_G2);

    k_diag<<<NE / 256, 256>>>(He, p);
    k_prep<<<(int)(((size_t)NV * NE) / 8 / 256), 256>>>(T);
    k_hvw<<<NV, OUT_V>>>(Hv, W);
    k_gemm1<<<NPAIR, NTH, SMEM_G1>>>(adjv);
    k_bias<<<NV * OUT_V / 256, 256>>>(out, bias);
    k_gemm2h<<<dim3(NV / BM, KSPLIT2), NTH, SMEM_G2>>>(out);

    if (out_size >= NV * OUT_V + NE * IN_E) {
        cudaMemcpyAsync(out + NV * OUT_V, He,
                        (size_t)NE * IN_E * sizeof(float),
                        cudaMemcpyDeviceToDevice, 0);
    }
}